// round 11
// baseline (speedup 1.0000x reference)
#include <cuda_runtime.h>
#include <cuda_bf16.h>
#include <cstdint>

// scratch (device globals) — b=4, c=512, l=4096
__device__ __nv_bfloat16 g_ht [4ull * 4096 * 512];  // H^T [b][l][c]
__device__ __nv_bfloat16 g_nkt[4ull * 4096 * 512];  // N = H^T M^T [b][l][c]
__device__ __nv_bfloat16 g_v2 [4ull * 512 * 4096];  // V2 = W2 H [b][c][l]
__device__ __nv_bfloat16 g_s  [4ull * 4096 * 4096]; // P = exp(scale*S)
__device__ __nv_bfloat16 g_wqT[512 * 512], g_wkT[512 * 512];
__device__ __nv_bfloat16 g_wvT[512 * 512], g_wpB[512 * 512];
__device__ __nv_bfloat16 g_M  [512 * 512], g_W2 [512 * 512];
__device__ float g_l[4 * 4096];                      // softmax row sums
__device__ float g_u[4 * 4096], g_vb[4 * 4096];      // rank-1 bias terms
__device__ float g_e1[512], g_e2[512], g_bpp[512], g_c0[1];

// ---------------- helpers ----------------------------------------------------
__device__ __forceinline__ uint32_t smem_u32(const void* p) {
    uint32_t a;
    asm("{ .reg .u64 t; cvta.to.shared.u64 t, %1; cvt.u32.u64 %0, t; }"
        : "=r"(a) : "l"(p));
    return a;
}

__device__ __forceinline__ void ldsm4(uint32_t& r0, uint32_t& r1, uint32_t& r2,
                                      uint32_t& r3, uint32_t addr) {
    asm volatile("ldmatrix.sync.aligned.m8n8.x4.shared.b16 {%0,%1,%2,%3}, [%4];"
                 : "=r"(r0), "=r"(r1), "=r"(r2), "=r"(r3) : "r"(addr));
}

__device__ __forceinline__ void mma_bf16(float (&c)[4], const uint32_t (&a)[4],
                                         const uint32_t (&b)[2]) {
    asm volatile(
        "mma.sync.aligned.m16n8k16.row.col.f32.bf16.bf16.f32 "
        "{%0,%1,%2,%3},{%4,%5,%6,%7},{%8,%9},{%0,%1,%2,%3};"
        : "+f"(c[0]), "+f"(c[1]), "+f"(c[2]), "+f"(c[3])
        : "r"(a[0]), "r"(a[1]), "r"(a[2]), "r"(a[3]), "r"(b[0]), "r"(b[1]));
}

// FFMA-only exp (no MUFU)
__device__ __forceinline__ float fexp(float x) {
    float t = fminf(fmaxf(x * 1.4426950408889634f, -125.0f), 125.0f);
    float fi = floorf(t);
    float f = t - fi;
    float p = 1.3333558146e-3f;
    p = p * f + 9.6181291076e-3f;
    p = p * f + 5.5504108664e-2f;
    p = p * f + 2.4022650696e-1f;
    p = p * f + 6.9314718056e-1f;
    p = p * f + 1.0f;
    return __int_as_float(__float_as_int(p) + ((int)fi << 23));
}

// smem: 3 stages x (A 128x(64+8) bf16 = 18432B, B same) = 110592B
#define ROW_B 144
#define A_BYTES 18432
#define STG_BYTES 36864
#define SMEM_TOTAL 110592

__device__ __forceinline__ void load_stage(
    uint32_t sbase, const __nv_bfloat16* __restrict__ Ab,
    const __nv_bfloat16* __restrict__ Bb, int64_t lda, int64_t ldb, int koff,
    int tid) {
#pragma unroll
    for (int rep = 0; rep < 8; rep++) {
        int u = tid + rep * 256;
        const __nv_bfloat16* g;
        uint32_t dst;
        if (u < 1024) {
            int row = u >> 3, c16 = u & 7;
            g = Ab + (int64_t)row * lda + koff + c16 * 8;
            dst = sbase + row * ROW_B + c16 * 16;
        } else {
            int vv = u - 1024;
            int row = vv >> 3, c16 = vv & 7;
            g = Bb + (int64_t)row * ldb + koff + c16 * 8;
            dst = sbase + A_BYTES + row * ROW_B + c16 * 16;
        }
        asm volatile("cp.async.cg.shared.global [%0], [%1], 16;"
                     :: "r"(dst), "l"(g) : "memory");
    }
}

// ---------------- generic bf16 tensor-core GEMM (R6 mainloop) ------------------
// CTA tile 128x128, 8 warps (64x32), BK=64, 3-stage.
// mode 0: C = alpha*acc (+bias_m[row])            (bf16 or f32 out)
// mode 1: p = fexp(alpha*acc + ub[z,row] + vb[z,col] + c0); bf16; row sums->lsum
// mode 3: C = alpha*acc / lsum[z,col] + bias_m[row] (+resid, f32 out)
__global__ void __launch_bounds__(256, 2) mm_bf16(
    const __nv_bfloat16* __restrict__ A, int64_t lda, int64_t astr,
    const __nv_bfloat16* __restrict__ B, int64_t ldb, int64_t bstr,
    void* __restrict__ C, int64_t ldc, int64_t cstr, int K, float alpha,
    const float* __restrict__ bias_m,
    const float* __restrict__ ub, const float* __restrict__ vbp,
    const float* __restrict__ c0p,
    const float* __restrict__ resid, float* __restrict__ lsum,
    int mode, int out_f32)
{
    extern __shared__ char smem[];
    uint32_t sb = smem_u32(smem);
    int tid = threadIdx.x, lane = tid & 31, wid = tid >> 5;
    int wm = wid & 1, wn = wid >> 1;
    int m0 = blockIdx.y * 128, n0 = blockIdx.x * 128, z = blockIdx.z;
    const __nv_bfloat16* Ab = A + (int64_t)z * astr + (int64_t)m0 * lda;
    const __nv_bfloat16* Bb = B + (int64_t)z * bstr + (int64_t)n0 * ldb;

    const int S = K >> 6;
    load_stage(sb, Ab, Bb, lda, ldb, 0, tid);
    asm volatile("cp.async.commit_group;" ::: "memory");
    if (S > 1) load_stage(sb + STG_BYTES, Ab, Bb, lda, ldb, 64, tid);
    asm volatile("cp.async.commit_group;" ::: "memory");

    float acc[4][4][4] = {};
    uint32_t a_row = wm * 64 + (lane & 15);
    uint32_t a_cs = ((lane >> 4) << 4);
    uint32_t b_row = wn * 32 + (lane & 7) + ((lane >> 4) << 3);
    uint32_t b_cs = (((lane >> 3) & 1) << 4);

    for (int s = 0; s < S; s++) {
        asm volatile("cp.async.wait_group 1;" ::: "memory");
        __syncthreads();
        if (s + 2 < S)
            load_stage(sb + ((s + 2) % 3) * STG_BYTES, Ab, Bb, lda, ldb,
                       (s + 2) * 64, tid);
        asm volatile("cp.async.commit_group;" ::: "memory");

        uint32_t sa = sb + (s % 3) * STG_BYTES;
        uint32_t sB = sa + A_BYTES;

        uint32_t afr[2][4][4];
#pragma unroll
        for (int i = 0; i < 4; i++)
            ldsm4(afr[0][i][0], afr[0][i][1], afr[0][i][2], afr[0][i][3],
                  sa + (a_row + i * 16) * ROW_B + a_cs);
#pragma unroll
        for (int kk = 0; kk < 4; kk++) {
            int cur = kk & 1;
            if (kk < 3) {
                int nxt = cur ^ 1;
#pragma unroll
                for (int i = 0; i < 4; i++)
                    ldsm4(afr[nxt][i][0], afr[nxt][i][1], afr[nxt][i][2],
                          afr[nxt][i][3],
                          sa + (a_row + i * 16) * ROW_B + (kk + 1) * 32 + a_cs);
            }
            uint32_t b[4][2];
#pragma unroll
            for (int jt = 0; jt < 2; jt++) {
                uint32_t r0, r1, r2, r3;
                ldsm4(r0, r1, r2, r3,
                      sB + (b_row + jt * 16) * ROW_B + kk * 32 + b_cs);
                b[jt * 2][0] = r0; b[jt * 2][1] = r1;
                b[jt * 2 + 1][0] = r2; b[jt * 2 + 1][1] = r3;
            }
#pragma unroll
            for (int i = 0; i < 4; i++)
#pragma unroll
                for (int j = 0; j < 4; j++) mma_bf16(acc[i][j], afr[cur][i], b[j]);
        }
    }

    // ---------------- epilogue ----------------
    float c0v = (mode == 1) ? c0p[0] : 0.0f;
#pragma unroll
    for (int i = 0; i < 4; i++) {
        int r0 = m0 + wm * 64 + i * 16 + (lane >> 2);
        float bm0 = bias_m ? bias_m[r0] : 0.0f;
        float bm1 = bias_m ? bias_m[r0 + 8] : 0.0f;
        float uu0 = 0.0f, uu1 = 0.0f;
        if (mode == 1) {
            uu0 = ub[z * 4096 + r0] + c0v;
            uu1 = ub[z * 4096 + r0 + 8] + c0v;
        }
        float rs0 = 0.0f, rs1 = 0.0f;
#pragma unroll
        for (int j = 0; j < 4; j++) {
            int cc = n0 + wn * 32 + j * 8 + (lane & 3) * 2;
            float v00, v01, v10, v11;
            if (mode == 1) {
                float vv0 = vbp[z * 4096 + cc], vv1 = vbp[z * 4096 + cc + 1];
                v00 = fexp(acc[i][j][0] * alpha + uu0 + vv0);
                v01 = fexp(acc[i][j][1] * alpha + uu0 + vv1);
                v10 = fexp(acc[i][j][2] * alpha + uu1 + vv0);
                v11 = fexp(acc[i][j][3] * alpha + uu1 + vv1);
            } else if (mode == 3) {
                float li0 = __fdividef(1.0f, lsum[z * 4096 + cc]);
                float li1 = __fdividef(1.0f, lsum[z * 4096 + cc + 1]);
                v00 = acc[i][j][0] * li0 + bm0;
                v01 = acc[i][j][1] * li1 + bm0;
                v10 = acc[i][j][2] * li0 + bm1;
                v11 = acc[i][j][3] * li1 + bm1;
            } else {
                v00 = acc[i][j][0] * alpha + bm0;
                v01 = acc[i][j][1] * alpha + bm0;
                v10 = acc[i][j][2] * alpha + bm1;
                v11 = acc[i][j][3] * alpha + bm1;
            }
            int64_t i0 = (int64_t)z * cstr + (int64_t)r0 * ldc + cc;
            int64_t i1 = i0 + 8 * ldc;
            if (out_f32) {
                float* Cf = (float*)C;
                if (resid) {
                    float2 t0 = *(const float2*)(resid + i0);
                    float2 t1 = *(const float2*)(resid + i1);
                    v00 += t0.x; v01 += t0.y; v10 += t1.x; v11 += t1.y;
                }
                *(float2*)(Cf + i0) = make_float2(v00, v01);
                *(float2*)(Cf + i1) = make_float2(v10, v11);
            } else {
                __nv_bfloat16* Cb = (__nv_bfloat16*)C;
                __nv_bfloat162 h0 = __float22bfloat162_rn(make_float2(v00, v01));
                __nv_bfloat162 h1 = __float22bfloat162_rn(make_float2(v10, v11));
                if (mode == 1) {
                    float2 q0 = __bfloat1622float2(h0);
                    float2 q1 = __bfloat1622float2(h1);
                    rs0 += q0.x + q0.y;
                    rs1 += q1.x + q1.y;
                }
                *(__nv_bfloat162*)(Cb + i0) = h0;
                *(__nv_bfloat162*)(Cb + i1) = h1;
            }
        }
        if (mode == 1) {
            rs0 += __shfl_xor_sync(0xffffffffu, rs0, 1);
            rs0 += __shfl_xor_sync(0xffffffffu, rs0, 2);
            rs1 += __shfl_xor_sync(0xffffffffu, rs1, 1);
            rs1 += __shfl_xor_sync(0xffffffffu, rs1, 2);
            if ((lane & 3) == 0) {
                atomicAdd(lsum + z * 4096 + r0, rs0);
                atomicAdd(lsum + z * 4096 + r0 + 8, rs1);
            }
        }
    }
}

// ---------------- zero the row-sum buffer -------------------------------------
__global__ void zero_l_kernel(float* __restrict__ l) {
    l[blockIdx.x * 1024 + threadIdx.x] = 0.0f;
}

// ---------------- weight prep: transpose+cvt wq,wk,wv; plain cvt wp ------------
__global__ void __launch_bounds__(256) prep_w_kernel(
    const float* __restrict__ wq, const float* __restrict__ wk,
    const float* __restrict__ wv, const float* __restrict__ wp,
    __nv_bfloat16* __restrict__ wqT, __nv_bfloat16* __restrict__ wkT,
    __nv_bfloat16* __restrict__ wvT, __nv_bfloat16* __restrict__ wpB)
{
    __shared__ float t[32][33];
    int zz = blockIdx.z;
    const float* src = zz == 0 ? wq : zz == 1 ? wk : zz == 2 ? wv : wp;
    int x0 = blockIdx.x * 32, y0 = blockIdx.y * 32;
    int tx = threadIdx.x & 31, ty = threadIdx.x >> 5;   // 32 x 8
    for (int r = ty; r < 32; r += 8)
        t[r][tx] = src[(int64_t)(y0 + r) * 512 + x0 + tx];
    __syncthreads();
    if (zz < 3) {
        __nv_bfloat16* dst = zz == 0 ? wqT : zz == 1 ? wkT : wvT;
        for (int r = ty; r < 32; r += 8)
            dst[(int64_t)(x0 + r) * 512 + y0 + tx] = __float2bfloat16(t[tx][r]);
    } else {
        for (int r = ty; r < 32; r += 8)
            wpB[(int64_t)(y0 + r) * 512 + x0 + tx] = __float2bfloat16(t[r][tx]);
    }
}

// ---------------- bias vectors: e1=scale*Wq^T bk, e2=scale*Wk^T bq,
//                  bpp = Wp bv + bp, c0 = scale * (bq . bk) ---------------------
__global__ void __launch_bounds__(256) vec_kernel(
    const float* __restrict__ wq, const float* __restrict__ wk,
    const float* __restrict__ wp, const float* __restrict__ bq,
    const float* __restrict__ bk, const float* __restrict__ bv,
    const float* __restrict__ bp, float* __restrict__ e1,
    float* __restrict__ e2, float* __restrict__ bpp,
    float* __restrict__ c0, float scale)
{
    int c = blockIdx.x * 256 + threadIdx.x;
    float s1 = 0.f, s2 = 0.f, s3 = 0.f;
    for (int e = 0; e < 512; e++) {
        s1 += wq[e * 512 + c] * bk[e];
        s2 += wk[e * 512 + c] * bq[e];
        s3 += wp[c * 512 + e] * bv[e];
    }
    e1[c] = s1 * scale;
    e2[c] = s2 * scale;
    bpp[c] = s3 + bp[c];
    if (c == 0) {
        float s = 0.f;
        for (int e = 0; e < 512; e++) s += bq[e] * bk[e];
        c0[0] = s * scale;
    }
}

// ---------------- GEMV: u[z][i] = ht_i . e1 ; v[z][i] = ht_i . e2 --------------
__global__ void __launch_bounds__(256) gemv_uv_kernel(
    const __nv_bfloat16* __restrict__ ht, const float* __restrict__ e1,
    const float* __restrict__ e2, float* __restrict__ u,
    float* __restrict__ vb)
{
    int z = blockIdx.y;
    int row = blockIdx.x * 8 + (threadIdx.x >> 5);
    int lane = threadIdx.x & 31;
    const __nv_bfloat16* hr = ht + (int64_t)z * 2097152 + (int64_t)row * 512;
    float s1 = 0.f, s2 = 0.f;
    for (int c = lane * 2; c < 512; c += 64) {
        float2 h = __bfloat1622float2(*(const __nv_bfloat162*)(hr + c));
        s1 += h.x * e1[c] + h.y * e1[c + 1];
        s2 += h.x * e2[c] + h.y * e2[c + 1];
    }
#pragma unroll
    for (int o = 16; o; o >>= 1) {
        s1 += __shfl_xor_sync(0xffffffffu, s1, o);
        s2 += __shfl_xor_sync(0xffffffffu, s2, o);
    }
    if (lane == 0) {
        u[z * 4096 + row] = s1;
        vb[z * 4096 + row] = s2;
    }
}

// ---------------- GroupNorm -> transposed bf16 H^T [b][l][c] -------------------
__global__ void __launch_bounds__(256) groupnorm_t_kernel(
    const float* __restrict__ x, const float* __restrict__ scale,
    const float* __restrict__ bias, __nv_bfloat16* __restrict__ ht)
{
    __shared__ float tile[16 * 257];
    __shared__ float sh_s[8], sh_ss[8], s_stat[2];
    __shared__ float csc[16], cbi[16];

    int bi = blockIdx.x;
    int b = bi >> 5, g = bi & 31;
    const float* xg = x + (size_t)bi * 65536;

    float s = 0.f, ss = 0.f;
    const float4* xp = (const float4*)xg;
    for (int i = threadIdx.x; i < 16384; i += 256) {
        float4 t = xp[i];
        s  += t.x + t.y + t.z + t.w;
        ss += t.x * t.x + t.y * t.y + t.z * t.z + t.w * t.w;
    }
    int lane = threadIdx.x & 31, wrp = threadIdx.x >> 5;
#pragma unroll
    for (int o = 16; o; o >>= 1) {
        s  += __shfl_xor_sync(0xffffffffu, s, o);
        ss += __shfl_xor_sync(0xffffffffu, ss, o);
    }
    if (lane == 0) { sh_s[wrp] = s; sh_ss[wrp] = ss; }
    __syncthreads();
    if (threadIdx.x == 0) {
        float ts = 0.f, tss = 0.f;
        for (int i = 0; i < 8; i++) { ts += sh_s[i]; tss += sh_ss[i]; }
        float mean = ts / 65536.0f;
        float var  = tss / 65536.0f - mean * mean;
        s_stat[0] = mean;
        s_stat[1] = rsqrtf(var + 1e-6f);
    }
    __syncthreads();
    if (threadIdx.x < 16) {
        float sc = scale[g * 16 + threadIdx.x] * s_stat[1];
        csc[threadIdx.x] = sc;
        cbi[threadIdx.x] = bias[g * 16 + threadIdx.x] - s_stat[0] * sc;
    }
    __syncthreads();

    __nv_bfloat16* hb = ht + (size_t)b * 2097152 + g * 16;
    for (int l0 = 0; l0 < 4096; l0 += 256) {
#pragma unroll
        for (int c = 0; c < 16; c++)
            tile[c * 257 + threadIdx.x] =
                xg[c * 4096 + l0 + threadIdx.x] * csc[c] + cbi[c];
        __syncthreads();
#pragma unroll
        for (int rep = 0; rep < 16; rep++) {
            int idx = rep * 256 + threadIdx.x;
            int lp = idx >> 4, cc = idx & 15;
            hb[(size_t)(l0 + lp) * 512 + cc] =
                __float2bfloat16(tile[cc * 257 + lp]);
        }
        __syncthreads();
    }
}

// -----------------------------------------------------------------------------
extern "C" void kernel_launch(void* const* d_in, const int* in_sizes, int n_in,
                              void* d_out, int out_size)
{
    (void)in_sizes; (void)n_in; (void)out_size;
    const float* x  = (const float*)d_in[0];
    const float* gs = (const float*)d_in[1];
    const float* gb = (const float*)d_in[2];
    const float* wq = (const float*)d_in[3];
    const float* bq = (const float*)d_in[4];
    const float* wk = (const float*)d_in[5];
    const float* bk = (const float*)d_in[6];
    const float* wv = (const float*)d_in[7];
    const float* bv = (const float*)d_in[8];
    const float* wp = (const float*)d_in[9];
    const float* bp = (const float*)d_in[10];
    float* out = (float*)d_out;

    __nv_bfloat16 *ht, *nkt, *v2, *s, *wqT, *wkT, *wvT, *wpB, *Mb, *W2;
    float *l, *u, *vb, *e1, *e2, *bpp, *c0;
    cudaGetSymbolAddress((void**)&ht, g_ht);
    cudaGetSymbolAddress((void**)&nkt, g_nkt);
    cudaGetSymbolAddress((void**)&v2, g_v2);
    cudaGetSymbolAddress((void**)&s,  g_s);
    cudaGetSymbolAddress((void**)&wqT, g_wqT);
    cudaGetSymbolAddress((void**)&wkT, g_wkT);
    cudaGetSymbolAddress((void**)&wvT, g_wvT);
    cudaGetSymbolAddress((void**)&wpB, g_wpB);
    cudaGetSymbolAddress((void**)&Mb, g_M);
    cudaGetSymbolAddress((void**)&W2, g_W2);
    cudaGetSymbolAddress((void**)&l,  g_l);
    cudaGetSymbolAddress((void**)&u,  g_u);
    cudaGetSymbolAddress((void**)&vb, g_vb);
    cudaGetSymbolAddress((void**)&e1, g_e1);
    cudaGetSymbolAddress((void**)&e2, g_e2);
    cudaGetSymbolAddress((void**)&bpp, g_bpp);
    cudaGetSymbolAddress((void**)&c0, g_c0);

    cudaFuncSetAttribute(mm_bf16, cudaFuncAttributeMaxDynamicSharedMemorySize,
                         SMEM_TOTAL);

    const float SCALE = 0.044194173824159216f;  // 512^-0.5
    const int64_t LC = 2097152, LS = 16777216;

    prep_w_kernel<<<dim3(16, 16, 4), 256>>>(wq, wk, wv, wp, wqT, wkT, wvT, wpB);
    groupnorm_t_kernel<<<128, 256>>>(x, gs, gb, ht);
    zero_l_kernel<<<16, 1024>>>(l);
    vec_kernel<<<2, 256>>>(wq, wk, wp, bq, bk, bv, bp, e1, e2, bpp, c0, SCALE);
    gemv_uv_kernel<<<dim3(512, 4), 256>>>(ht, e1, e2, u, vb);

    // M[c][d] = sum_e wq[e][c] wk[e][d] : 512x512x512
    mm_bf16<<<dim3(4, 4, 1), 256, SMEM_TOTAL>>>(wqT, 512, 0, wkT, 512, 0,
        Mb, 512, 0, 512, 1.0f, nullptr, nullptr, nullptr, nullptr, nullptr,
        nullptr, 0, 0);
    // W2[c][d] = sum_e wp[c][e] wv[e][d] : 512x512x512
    mm_bf16<<<dim3(4, 4, 1), 256, SMEM_TOTAL>>>(wpB, 512, 0, wvT, 512, 0,
        W2, 512, 0, 512, 1.0f, nullptr, nullptr, nullptr, nullptr, nullptr,
        nullptr, 0, 0);
    // N[j][c'] = sum_d M[c'][d] ht[j][d] : M=4096, N=512, K=512
    mm_bf16<<<dim3(4, 32, 4), 256, SMEM_TOTAL>>>(ht, 512, LC, Mb, 512, 0,
        nkt, 512, LC, 512, 1.0f, nullptr, nullptr, nullptr, nullptr, nullptr,
        nullptr, 0, 0);
    // V2[c][j] = sum_d W2[c][d] ht[j][d] : M=512, N=4096, K=512
    mm_bf16<<<dim3(32, 4, 4), 256, SMEM_TOTAL>>>(W2, 512, 0, ht, 512, LC,
        v2, 4096, LC, 512, 1.0f, nullptr, nullptr, nullptr, nullptr, nullptr,
        nullptr, 0, 0);
    // P[i][j] = exp(scale*acc + u_i + v_j + c0) : M=N=4096, K=512 (+ row sums)
    mm_bf16<<<dim3(32, 32, 4), 256, SMEM_TOTAL>>>(ht, 512, LC, nkt, 512, LC,
        s, 4096, LS, 512, SCALE, nullptr, u, vb, c0, nullptr, l, 1, 0);
    // out[c][i] = (sum_j V2[c][j] P[i][j]) / l[i] + bpp[c] + x[c][i]
    mm_bf16<<<dim3(32, 4, 4), 256, SMEM_TOTAL>>>(v2, 4096, LC, s, 4096, LS,
        out, 4096, LC, 4096, 1.0f, bpp, nullptr, nullptr, nullptr, x, l, 3, 1);
}

// round 12
// speedup vs baseline: 1.1903x; 1.1903x over previous
#include <cuda_runtime.h>
#include <cuda_bf16.h>
#include <cstdint>

// scratch (device globals) — b=4, c=512, l=4096
__device__ __nv_bfloat16 g_ht [4ull * 4096 * 512];  // H^T [b][l][c]
__device__ __nv_bfloat16 g_nkt[4ull * 4096 * 512];  // N = H^T M^T [b][l][c]
__device__ __nv_bfloat16 g_v2 [4ull * 512 * 4096];  // V2 = W2 H [b][c][l]
__device__ __nv_bfloat16 g_s  [4ull * 4096 * 4096]; // P = exp(scale*S)
__device__ __nv_bfloat16 g_wqT[512 * 512], g_wkT[512 * 512];
__device__ __nv_bfloat16 g_wvT[512 * 512], g_wpB[512 * 512];
__device__ __nv_bfloat16 g_M  [512 * 512], g_W2 [512 * 512];
__device__ float g_l[4 * 4096];                      // softmax row sums
__device__ float g_u[4 * 4096], g_vb[4 * 4096];      // rank-1 bias terms
__device__ float g_e1[512], g_e2[512], g_bpp[512], g_c0[1];

// ---------------- helpers ----------------------------------------------------
__device__ __forceinline__ uint32_t smem_u32(const void* p) {
    uint32_t a;
    asm("{ .reg .u64 t; cvta.to.shared.u64 t, %1; cvt.u32.u64 %0, t; }"
        : "=r"(a) : "l"(p));
    return a;
}

__device__ __forceinline__ void ldsm4(uint32_t& r0, uint32_t& r1, uint32_t& r2,
                                      uint32_t& r3, uint32_t addr) {
    asm volatile("ldmatrix.sync.aligned.m8n8.x4.shared.b16 {%0,%1,%2,%3}, [%4];"
                 : "=r"(r0), "=r"(r1), "=r"(r2), "=r"(r3) : "r"(addr));
}

__device__ __forceinline__ void mma_bf16(float (&c)[4], const uint32_t (&a)[4],
                                         const uint32_t (&b)[2]) {
    asm volatile(
        "mma.sync.aligned.m16n8k16.row.col.f32.bf16.bf16.f32 "
        "{%0,%1,%2,%3},{%4,%5,%6,%7},{%8,%9},{%0,%1,%2,%3};"
        : "+f"(c[0]), "+f"(c[1]), "+f"(c[2]), "+f"(c[3])
        : "r"(a[0]), "r"(a[1]), "r"(a[2]), "r"(a[3]), "r"(b[0]), "r"(b[1]));
}

// FFMA-only exp (no MUFU)
__device__ __forceinline__ float fexp(float x) {
    float t = fminf(fmaxf(x * 1.4426950408889634f, -125.0f), 125.0f);
    float fi = floorf(t);
    float f = t - fi;
    float p = 1.3333558146e-3f;
    p = p * f + 9.6181291076e-3f;
    p = p * f + 5.5504108664e-2f;
    p = p * f + 2.4022650696e-1f;
    p = p * f + 6.9314718056e-1f;
    p = p * f + 1.0f;
    return __int_as_float(__float_as_int(p) + ((int)fi << 23));
}

// smem: 3 stages x (A 128x(64+8) bf16 = 18432B, B same) = 110592B
#define ROW_B 144
#define A_BYTES 18432
#define STG_BYTES 36864
#define SMEM_TOTAL 110592

__device__ __forceinline__ void load_stage(
    uint32_t sbase, const __nv_bfloat16* __restrict__ Ab,
    const __nv_bfloat16* __restrict__ Bb, int64_t lda, int64_t ldb, int koff,
    int tid) {
#pragma unroll
    for (int rep = 0; rep < 8; rep++) {
        int u = tid + rep * 256;
        const __nv_bfloat16* g;
        uint32_t dst;
        if (u < 1024) {
            int row = u >> 3, c16 = u & 7;
            g = Ab + (int64_t)row * lda + koff + c16 * 8;
            dst = sbase + row * ROW_B + c16 * 16;
        } else {
            int vv = u - 1024;
            int row = vv >> 3, c16 = vv & 7;
            g = Bb + (int64_t)row * ldb + koff + c16 * 8;
            dst = sbase + A_BYTES + row * ROW_B + c16 * 16;
        }
        asm volatile("cp.async.cg.shared.global [%0], [%1], 16;"
                     :: "r"(dst), "l"(g) : "memory");
    }
}

// ---------------- generic bf16 tensor-core GEMM (R6 mainloop) ------------------
// CTA tile 128x128, 8 warps (64x32), BK=64, 3-stage.
// mode 0: C = alpha*acc (+bias_m[row])            (bf16 or f32 out)
// mode 1: p = fexp(alpha*acc + ub[z,row] + vb[z,col] + c0); bf16; row sums->lsum
// mode 3: C = alpha*acc / lsum[z,col] + bias_m[row] (+resid, f32 out)
__global__ void __launch_bounds__(256, 2) mm_bf16(
    const __nv_bfloat16* __restrict__ A, int64_t lda, int64_t astr,
    const __nv_bfloat16* __restrict__ B, int64_t ldb, int64_t bstr,
    void* __restrict__ C, int64_t ldc, int64_t cstr, int K, float alpha,
    const float* __restrict__ bias_m,
    const float* __restrict__ ub, const float* __restrict__ vbp,
    const float* __restrict__ c0p,
    const float* __restrict__ resid, float* __restrict__ lsum,
    int mode, int out_f32)
{
    extern __shared__ char smem[];
    uint32_t sb = smem_u32(smem);
    int tid = threadIdx.x, lane = tid & 31, wid = tid >> 5;
    int wm = wid & 1, wn = wid >> 1;
    int m0 = blockIdx.y * 128, n0 = blockIdx.x * 128, z = blockIdx.z;
    const __nv_bfloat16* Ab = A + (int64_t)z * astr + (int64_t)m0 * lda;
    const __nv_bfloat16* Bb = B + (int64_t)z * bstr + (int64_t)n0 * ldb;

    const int S = K >> 6;
    load_stage(sb, Ab, Bb, lda, ldb, 0, tid);
    asm volatile("cp.async.commit_group;" ::: "memory");
    if (S > 1) load_stage(sb + STG_BYTES, Ab, Bb, lda, ldb, 64, tid);
    asm volatile("cp.async.commit_group;" ::: "memory");

    float acc[4][4][4] = {};
    uint32_t a_row = wm * 64 + (lane & 15);
    uint32_t a_cs = ((lane >> 4) << 4);
    uint32_t b_row = wn * 32 + (lane & 7) + ((lane >> 4) << 3);
    uint32_t b_cs = (((lane >> 3) & 1) << 4);

    for (int s = 0; s < S; s++) {
        asm volatile("cp.async.wait_group 1;" ::: "memory");
        __syncthreads();
        if (s + 2 < S)
            load_stage(sb + ((s + 2) % 3) * STG_BYTES, Ab, Bb, lda, ldb,
                       (s + 2) * 64, tid);
        asm volatile("cp.async.commit_group;" ::: "memory");

        uint32_t sa = sb + (s % 3) * STG_BYTES;
        uint32_t sB = sa + A_BYTES;

        uint32_t afr[2][4][4];
#pragma unroll
        for (int i = 0; i < 4; i++)
            ldsm4(afr[0][i][0], afr[0][i][1], afr[0][i][2], afr[0][i][3],
                  sa + (a_row + i * 16) * ROW_B + a_cs);
#pragma unroll
        for (int kk = 0; kk < 4; kk++) {
            int cur = kk & 1;
            if (kk < 3) {
                int nxt = cur ^ 1;
#pragma unroll
                for (int i = 0; i < 4; i++)
                    ldsm4(afr[nxt][i][0], afr[nxt][i][1], afr[nxt][i][2],
                          afr[nxt][i][3],
                          sa + (a_row + i * 16) * ROW_B + (kk + 1) * 32 + a_cs);
            }
            uint32_t b[4][2];
#pragma unroll
            for (int jt = 0; jt < 2; jt++) {
                uint32_t r0, r1, r2, r3;
                ldsm4(r0, r1, r2, r3,
                      sB + (b_row + jt * 16) * ROW_B + kk * 32 + b_cs);
                b[jt * 2][0] = r0; b[jt * 2][1] = r1;
                b[jt * 2 + 1][0] = r2; b[jt * 2 + 1][1] = r3;
            }
#pragma unroll
            for (int i = 0; i < 4; i++)
#pragma unroll
                for (int j = 0; j < 4; j++) mma_bf16(acc[i][j], afr[cur][i], b[j]);
        }
    }

    // ---------------- epilogue ----------------
    float c0v = (mode == 1) ? c0p[0] : 0.0f;
#pragma unroll
    for (int i = 0; i < 4; i++) {
        int r0 = m0 + wm * 64 + i * 16 + (lane >> 2);
        float bm0 = bias_m ? bias_m[r0] : 0.0f;
        float bm1 = bias_m ? bias_m[r0 + 8] : 0.0f;
        float uu0 = 0.0f, uu1 = 0.0f;
        if (mode == 1) {
            uu0 = ub[z * 4096 + r0] + c0v;
            uu1 = ub[z * 4096 + r0 + 8] + c0v;
        }
        float rs0 = 0.0f, rs1 = 0.0f;
#pragma unroll
        for (int j = 0; j < 4; j++) {
            int cc = n0 + wn * 32 + j * 8 + (lane & 3) * 2;
            float v00, v01, v10, v11;
            if (mode == 1) {
                float vv0 = vbp[z * 4096 + cc], vv1 = vbp[z * 4096 + cc + 1];
                v00 = fexp(acc[i][j][0] * alpha + uu0 + vv0);
                v01 = fexp(acc[i][j][1] * alpha + uu0 + vv1);
                v10 = fexp(acc[i][j][2] * alpha + uu1 + vv0);
                v11 = fexp(acc[i][j][3] * alpha + uu1 + vv1);
            } else if (mode == 3) {
                float li0 = __fdividef(1.0f, lsum[z * 4096 + cc]);
                float li1 = __fdividef(1.0f, lsum[z * 4096 + cc + 1]);
                v00 = acc[i][j][0] * li0 + bm0;
                v01 = acc[i][j][1] * li1 + bm0;
                v10 = acc[i][j][2] * li0 + bm1;
                v11 = acc[i][j][3] * li1 + bm1;
            } else {
                v00 = acc[i][j][0] * alpha + bm0;
                v01 = acc[i][j][1] * alpha + bm0;
                v10 = acc[i][j][2] * alpha + bm1;
                v11 = acc[i][j][3] * alpha + bm1;
            }
            int64_t i0 = (int64_t)z * cstr + (int64_t)r0 * ldc + cc;
            int64_t i1 = i0 + 8 * ldc;
            if (out_f32) {
                float* Cf = (float*)C;
                if (resid) {
                    float2 t0 = *(const float2*)(resid + i0);
                    float2 t1 = *(const float2*)(resid + i1);
                    v00 += t0.x; v01 += t0.y; v10 += t1.x; v11 += t1.y;
                }
                *(float2*)(Cf + i0) = make_float2(v00, v01);
                *(float2*)(Cf + i1) = make_float2(v10, v11);
            } else {
                __nv_bfloat16* Cb = (__nv_bfloat16*)C;
                __nv_bfloat162 h0 = __float22bfloat162_rn(make_float2(v00, v01));
                __nv_bfloat162 h1 = __float22bfloat162_rn(make_float2(v10, v11));
                if (mode == 1) {
                    float2 q0 = __bfloat1622float2(h0);
                    float2 q1 = __bfloat1622float2(h1);
                    rs0 += q0.x + q0.y;
                    rs1 += q1.x + q1.y;
                }
                *(__nv_bfloat162*)(Cb + i0) = h0;
                *(__nv_bfloat162*)(Cb + i1) = h1;
            }
        }
        if (mode == 1) {
            rs0 += __shfl_xor_sync(0xffffffffu, rs0, 1);
            rs0 += __shfl_xor_sync(0xffffffffu, rs0, 2);
            rs1 += __shfl_xor_sync(0xffffffffu, rs1, 1);
            rs1 += __shfl_xor_sync(0xffffffffu, rs1, 2);
            if ((lane & 3) == 0) {
                atomicAdd(lsum + z * 4096 + r0, rs0);
                atomicAdd(lsum + z * 4096 + r0 + 8, rs1);
            }
        }
    }
}

// ---------------- zero the row-sum buffer -------------------------------------
__global__ void zero_l_kernel(float* __restrict__ l) {
    l[blockIdx.x * 1024 + threadIdx.x] = 0.0f;
}

// ---------------- weight prep: transpose+cvt wq,wk,wv; plain cvt wp ------------
__global__ void __launch_bounds__(256) prep_w_kernel(
    const float* __restrict__ wq, const float* __restrict__ wk,
    const float* __restrict__ wv, const float* __restrict__ wp,
    __nv_bfloat16* __restrict__ wqT, __nv_bfloat16* __restrict__ wkT,
    __nv_bfloat16* __restrict__ wvT, __nv_bfloat16* __restrict__ wpB)
{
    __shared__ float t[32][33];
    int zz = blockIdx.z;
    const float* src = zz == 0 ? wq : zz == 1 ? wk : zz == 2 ? wv : wp;
    int x0 = blockIdx.x * 32, y0 = blockIdx.y * 32;
    int tx = threadIdx.x & 31, ty = threadIdx.x >> 5;   // 32 x 8
    for (int r = ty; r < 32; r += 8)
        t[r][tx] = src[(int64_t)(y0 + r) * 512 + x0 + tx];
    __syncthreads();
    if (zz < 3) {
        __nv_bfloat16* dst = zz == 0 ? wqT : zz == 1 ? wkT : wvT;
        for (int r = ty; r < 32; r += 8)
            dst[(int64_t)(x0 + r) * 512 + y0 + tx] = __float2bfloat16(t[tx][r]);
    } else {
        for (int r = ty; r < 32; r += 8)
            wpB[(int64_t)(y0 + r) * 512 + x0 + tx] = __float2bfloat16(t[r][tx]);
    }
}

// ---------------- bias vectors (warp per channel): e1=scale*Wq^T bk,
//      e2=scale*Wk^T bq, bpp = Wp bv + bp, c0 = scale * (bq . bk) --------------
__global__ void __launch_bounds__(256) vec_kernel(
    const float* __restrict__ wq, const float* __restrict__ wk,
    const float* __restrict__ wp, const float* __restrict__ bq,
    const float* __restrict__ bk, const float* __restrict__ bv,
    const float* __restrict__ bp, float* __restrict__ e1,
    float* __restrict__ e2, float* __restrict__ bpp,
    float* __restrict__ c0, float scale)
{
    int wid = threadIdx.x >> 5, lane = threadIdx.x & 31;
    int c = blockIdx.x * 8 + wid;     // 64 blocks x 8 warps = 512 channels
    float s1 = 0.f, s2 = 0.f, s3 = 0.f, s4 = 0.f;
    for (int e = lane; e < 512; e += 32) {
        float bke = bk[e], bqe = bq[e];
        s1 += wq[e * 512 + c] * bke;
        s2 += wk[e * 512 + c] * bqe;
        s3 += wp[c * 512 + e] * bv[e];
        if (blockIdx.x == 0 && wid == 0) s4 += bqe * bke;
    }
#pragma unroll
    for (int o = 16; o; o >>= 1) {
        s1 += __shfl_xor_sync(0xffffffffu, s1, o);
        s2 += __shfl_xor_sync(0xffffffffu, s2, o);
        s3 += __shfl_xor_sync(0xffffffffu, s3, o);
        s4 += __shfl_xor_sync(0xffffffffu, s4, o);
    }
    if (lane == 0) {
        e1[c] = s1 * scale;
        e2[c] = s2 * scale;
        bpp[c] = s3 + bp[c];
        if (blockIdx.x == 0 && wid == 0) c0[0] = s4 * scale;
    }
}

// ---------------- GEMV: u[z][i] = ht_i . e1 ; v[z][i] = ht_i . e2 --------------
__global__ void __launch_bounds__(256) gemv_uv_kernel(
    const __nv_bfloat16* __restrict__ ht, const float* __restrict__ e1,
    const float* __restrict__ e2, float* __restrict__ u,
    float* __restrict__ vb)
{
    int z = blockIdx.y;
    int row = blockIdx.x * 8 + (threadIdx.x >> 5);
    int lane = threadIdx.x & 31;
    const __nv_bfloat16* hr = ht + (int64_t)z * 2097152 + (int64_t)row * 512;
    float s1 = 0.f, s2 = 0.f;
    for (int c = lane * 2; c < 512; c += 64) {
        float2 h = __bfloat1622float2(*(const __nv_bfloat162*)(hr + c));
        s1 += h.x * e1[c] + h.y * e1[c + 1];
        s2 += h.x * e2[c] + h.y * e2[c + 1];
    }
#pragma unroll
    for (int o = 16; o; o >>= 1) {
        s1 += __shfl_xor_sync(0xffffffffu, s1, o);
        s2 += __shfl_xor_sync(0xffffffffu, s2, o);
    }
    if (lane == 0) {
        u[z * 4096 + row] = s1;
        vb[z * 4096 + row] = s2;
    }
}

// ---------------- GroupNorm -> transposed bf16 H^T [b][l][c] -------------------
__global__ void __launch_bounds__(256) groupnorm_t_kernel(
    const float* __restrict__ x, const float* __restrict__ scale,
    const float* __restrict__ bias, __nv_bfloat16* __restrict__ ht)
{
    __shared__ float tile[16 * 257];
    __shared__ float sh_s[8], sh_ss[8], s_stat[2];
    __shared__ float csc[16], cbi[16];

    int bi = blockIdx.x;
    int b = bi >> 5, g = bi & 31;
    const float* xg = x + (size_t)bi * 65536;

    float s = 0.f, ss = 0.f;
    const float4* xp = (const float4*)xg;
    for (int i = threadIdx.x; i < 16384; i += 256) {
        float4 t = xp[i];
        s  += t.x + t.y + t.z + t.w;
        ss += t.x * t.x + t.y * t.y + t.z * t.z + t.w * t.w;
    }
    int lane = threadIdx.x & 31, wrp = threadIdx.x >> 5;
#pragma unroll
    for (int o = 16; o; o >>= 1) {
        s  += __shfl_xor_sync(0xffffffffu, s, o);
        ss += __shfl_xor_sync(0xffffffffu, ss, o);
    }
    if (lane == 0) { sh_s[wrp] = s; sh_ss[wrp] = ss; }
    __syncthreads();
    if (threadIdx.x == 0) {
        float ts = 0.f, tss = 0.f;
        for (int i = 0; i < 8; i++) { ts += sh_s[i]; tss += sh_ss[i]; }
        float mean = ts / 65536.0f;
        float var  = tss / 65536.0f - mean * mean;
        s_stat[0] = mean;
        s_stat[1] = rsqrtf(var + 1e-6f);
    }
    __syncthreads();
    if (threadIdx.x < 16) {
        float sc = scale[g * 16 + threadIdx.x] * s_stat[1];
        csc[threadIdx.x] = sc;
        cbi[threadIdx.x] = bias[g * 16 + threadIdx.x] - s_stat[0] * sc;
    }
    __syncthreads();

    __nv_bfloat16* hb = ht + (size_t)b * 2097152 + g * 16;
    for (int l0 = 0; l0 < 4096; l0 += 256) {
#pragma unroll
        for (int c = 0; c < 16; c++)
            tile[c * 257 + threadIdx.x] =
                xg[c * 4096 + l0 + threadIdx.x] * csc[c] + cbi[c];
        __syncthreads();
#pragma unroll
        for (int rep = 0; rep < 16; rep++) {
            int idx = rep * 256 + threadIdx.x;
            int lp = idx >> 4, cc = idx & 15;
            hb[(size_t)(l0 + lp) * 512 + cc] =
                __float2bfloat16(tile[cc * 257 + lp]);
        }
        __syncthreads();
    }
}

// -----------------------------------------------------------------------------
extern "C" void kernel_launch(void* const* d_in, const int* in_sizes, int n_in,
                              void* d_out, int out_size)
{
    (void)in_sizes; (void)n_in; (void)out_size;
    const float* x  = (const float*)d_in[0];
    const float* gs = (const float*)d_in[1];
    const float* gb = (const float*)d_in[2];
    const float* wq = (const float*)d_in[3];
    const float* bq = (const float*)d_in[4];
    const float* wk = (const float*)d_in[5];
    const float* bk = (const float*)d_in[6];
    const float* wv = (const float*)d_in[7];
    const float* bv = (const float*)d_in[8];
    const float* wp = (const float*)d_in[9];
    const float* bp = (const float*)d_in[10];
    float* out = (float*)d_out;

    __nv_bfloat16 *ht, *nkt, *v2, *s, *wqT, *wkT, *wvT, *wpB, *Mb, *W2;
    float *l, *u, *vb, *e1, *e2, *bpp, *c0;
    cudaGetSymbolAddress((void**)&ht, g_ht);
    cudaGetSymbolAddress((void**)&nkt, g_nkt);
    cudaGetSymbolAddress((void**)&v2, g_v2);
    cudaGetSymbolAddress((void**)&s,  g_s);
    cudaGetSymbolAddress((void**)&wqT, g_wqT);
    cudaGetSymbolAddress((void**)&wkT, g_wkT);
    cudaGetSymbolAddress((void**)&wvT, g_wvT);
    cudaGetSymbolAddress((void**)&wpB, g_wpB);
    cudaGetSymbolAddress((void**)&Mb, g_M);
    cudaGetSymbolAddress((void**)&W2, g_W2);
    cudaGetSymbolAddress((void**)&l,  g_l);
    cudaGetSymbolAddress((void**)&u,  g_u);
    cudaGetSymbolAddress((void**)&vb, g_vb);
    cudaGetSymbolAddress((void**)&e1, g_e1);
    cudaGetSymbolAddress((void**)&e2, g_e2);
    cudaGetSymbolAddress((void**)&bpp, g_bpp);
    cudaGetSymbolAddress((void**)&c0, g_c0);

    cudaFuncSetAttribute(mm_bf16, cudaFuncAttributeMaxDynamicSharedMemorySize,
                         SMEM_TOTAL);

    const float SCALE = 0.044194173824159216f;  // 512^-0.5
    const int64_t LC = 2097152, LS = 16777216;

    prep_w_kernel<<<dim3(16, 16, 4), 256>>>(wq, wk, wv, wp, wqT, wkT, wvT, wpB);
    groupnorm_t_kernel<<<128, 256>>>(x, gs, gb, ht);
    zero_l_kernel<<<16, 1024>>>(l);
    vec_kernel<<<64, 256>>>(wq, wk, wp, bq, bk, bv, bp, e1, e2, bpp, c0, SCALE);
    gemv_uv_kernel<<<dim3(512, 4), 256>>>(ht, e1, e2, u, vb);

    // M[c][d] = sum_e wq[e][c] wk[e][d] : 512x512x512
    mm_bf16<<<dim3(4, 4, 1), 256, SMEM_TOTAL>>>(wqT, 512, 0, wkT, 512, 0,
        Mb, 512, 0, 512, 1.0f, nullptr, nullptr, nullptr, nullptr, nullptr,
        nullptr, 0, 0);
    // W2[c][d] = sum_e wp[c][e] wv[e][d] : 512x512x512
    mm_bf16<<<dim3(4, 4, 1), 256, SMEM_TOTAL>>>(wpB, 512, 0, wvT, 512, 0,
        W2, 512, 0, 512, 1.0f, nullptr, nullptr, nullptr, nullptr, nullptr,
        nullptr, 0, 0);
    // N[j][c'] = sum_d M[c'][d] ht[j][d] : M=4096, N=512, K=512
    mm_bf16<<<dim3(4, 32, 4), 256, SMEM_TOTAL>>>(ht, 512, LC, Mb, 512, 0,
        nkt, 512, LC, 512, 1.0f, nullptr, nullptr, nullptr, nullptr, nullptr,
        nullptr, 0, 0);
    // V2[c][j] = sum_d W2[c][d] ht[j][d] : M=512, N=4096, K=512
    mm_bf16<<<dim3(32, 4, 4), 256, SMEM_TOTAL>>>(W2, 512, 0, ht, 512, LC,
        v2, 4096, LC, 512, 1.0f, nullptr, nullptr, nullptr, nullptr, nullptr,
        nullptr, 0, 0);
    // P[i][j] = exp(scale*acc + u_i + v_j + c0) : M=N=4096, K=512 (+ row sums)
    mm_bf16<<<dim3(32, 32, 4), 256, SMEM_TOTAL>>>(ht, 512, LC, nkt, 512, LC,
        s, 4096, LS, 512, SCALE, nullptr, u, vb, c0, nullptr, l, 1, 0);
    // out[c][i] = (sum_j V2[c][j] P[i][j]) / l[i] + bpp[c] + x[c][i]
    mm_bf16<<<dim3(32, 4, 4), 256, SMEM_TOTAL>>>(v2, 4096, LC, s, 4096, LS,
        out, 4096, LC, 4096, 1.0f, bpp, nullptr, nullptr, nullptr, x, l, 3, 1);
}

// round 13
// speedup vs baseline: 1.2607x; 1.0591x over previous
#include <cuda_runtime.h>
#include <cuda_bf16.h>
#include <cstdint>

// scratch (device globals) — b=4, c=512, l=4096
__device__ __nv_bfloat16 g_ht [4ull * 4096 * 512];  // H^T [b][l][c]
__device__ __nv_bfloat16 g_nkt[4ull * 4096 * 512];  // N = H^T M^T [b][l][c]
__device__ __nv_bfloat16 g_v2 [4ull * 512 * 4096];  // V2 = W2 H [b][c][l]
__device__ __nv_bfloat16 g_s  [4ull * 4096 * 4096]; // P = exp(scale*S)
__device__ __nv_bfloat16 g_wqT[512 * 512], g_wkT[512 * 512];
__device__ __nv_bfloat16 g_wvT[512 * 512], g_wpB[512 * 512];
__device__ __nv_bfloat16 g_M  [512 * 512], g_W2 [512 * 512];
__device__ float g_l[4 * 4096];                      // softmax row sums
__device__ float g_u[4 * 4096], g_vb[4 * 4096];      // rank-1 bias terms
__device__ float g_e12[1024];                        // [e1(512); e2(512)]
__device__ float g_bpp[512], g_c0[1];

// ---------------- helpers ----------------------------------------------------
__device__ __forceinline__ uint32_t smem_u32(const void* p) {
    uint32_t a;
    asm("{ .reg .u64 t; cvta.to.shared.u64 t, %1; cvt.u32.u64 %0, t; }"
        : "=r"(a) : "l"(p));
    return a;
}

__device__ __forceinline__ void ldsm4(uint32_t& r0, uint32_t& r1, uint32_t& r2,
                                      uint32_t& r3, uint32_t addr) {
    asm volatile("ldmatrix.sync.aligned.m8n8.x4.shared.b16 {%0,%1,%2,%3}, [%4];"
                 : "=r"(r0), "=r"(r1), "=r"(r2), "=r"(r3) : "r"(addr));
}

__device__ __forceinline__ void mma_bf16(float (&c)[4], const uint32_t (&a)[4],
                                         const uint32_t (&b)[2]) {
    asm volatile(
        "mma.sync.aligned.m16n8k16.row.col.f32.bf16.bf16.f32 "
        "{%0,%1,%2,%3},{%4,%5,%6,%7},{%8,%9},{%0,%1,%2,%3};"
        : "+f"(c[0]), "+f"(c[1]), "+f"(c[2]), "+f"(c[3])
        : "r"(a[0]), "r"(a[1]), "r"(a[2]), "r"(a[3]), "r"(b[0]), "r"(b[1]));
}

// FFMA-only exp (no MUFU)
__device__ __forceinline__ float fexp(float x) {
    float t = fminf(fmaxf(x * 1.4426950408889634f, -125.0f), 125.0f);
    float fi = floorf(t);
    float f = t - fi;
    float p = 1.3333558146e-3f;
    p = p * f + 9.6181291076e-3f;
    p = p * f + 5.5504108664e-2f;
    p = p * f + 2.4022650696e-1f;
    p = p * f + 6.9314718056e-1f;
    p = p * f + 1.0f;
    return __int_as_float(__float_as_int(p) + ((int)fi << 23));
}

// smem: 3 stages x (A 128x(64+8) bf16 = 18432B, B same) = 110592B
#define ROW_B 144
#define A_BYTES 18432
#define STG_BYTES 36864
#define SMEM_TOTAL 110592

__device__ __forceinline__ void load_stage(
    uint32_t sbase, const __nv_bfloat16* __restrict__ Ab,
    const __nv_bfloat16* __restrict__ Bb, int64_t lda, int64_t ldb, int koff,
    int tid) {
#pragma unroll
    for (int rep = 0; rep < 8; rep++) {
        int u = tid + rep * 256;
        const __nv_bfloat16* g;
        uint32_t dst;
        if (u < 1024) {
            int row = u >> 3, c16 = u & 7;
            g = Ab + (int64_t)row * lda + koff + c16 * 8;
            dst = sbase + row * ROW_B + c16 * 16;
        } else {
            int vv = u - 1024;
            int row = vv >> 3, c16 = vv & 7;
            g = Bb + (int64_t)row * ldb + koff + c16 * 8;
            dst = sbase + A_BYTES + row * ROW_B + c16 * 16;
        }
        asm volatile("cp.async.cg.shared.global [%0], [%1], 16;"
                     :: "r"(dst), "l"(g) : "memory");
    }
}

// ---------------- generic bf16 tensor-core GEMM (R6 mainloop) ------------------
// CTA tile 128x128, 8 warps (64x32), BK=64, 3-stage.
// mode 0: C = alpha*acc (+bias_m[row])
// mode 1: p = fexp(alpha*acc + ub[z,row] + vb[z,col] + c0); bf16; row sums->lsum
// mode 3: C = alpha*acc / lsum[z,col] + bias_m[row] (+resid, f32 out)
__global__ void __launch_bounds__(256, 2) mm_bf16(
    const __nv_bfloat16* __restrict__ A, int64_t lda, int64_t astr,
    const __nv_bfloat16* __restrict__ B, int64_t ldb, int64_t bstr,
    void* __restrict__ C, int64_t ldc, int64_t cstr, int K, float alpha,
    const float* __restrict__ bias_m,
    const float* __restrict__ ub, const float* __restrict__ vbp,
    const float* __restrict__ c0p,
    const float* __restrict__ resid, float* __restrict__ lsum,
    int mode, int out_f32)
{
    extern __shared__ char smem[];
    uint32_t sb = smem_u32(smem);
    int tid = threadIdx.x, lane = tid & 31, wid = tid >> 5;
    int wm = wid & 1, wn = wid >> 1;
    int m0 = blockIdx.y * 128, n0 = blockIdx.x * 128, z = blockIdx.z;
    const __nv_bfloat16* Ab = A + (int64_t)z * astr + (int64_t)m0 * lda;
    const __nv_bfloat16* Bb = B + (int64_t)z * bstr + (int64_t)n0 * ldb;

    const int S = K >> 6;
    load_stage(sb, Ab, Bb, lda, ldb, 0, tid);
    asm volatile("cp.async.commit_group;" ::: "memory");
    if (S > 1) load_stage(sb + STG_BYTES, Ab, Bb, lda, ldb, 64, tid);
    asm volatile("cp.async.commit_group;" ::: "memory");

    float acc[4][4][4] = {};
    uint32_t a_row = wm * 64 + (lane & 15);
    uint32_t a_cs = ((lane >> 4) << 4);
    uint32_t b_row = wn * 32 + (lane & 7) + ((lane >> 4) << 3);
    uint32_t b_cs = (((lane >> 3) & 1) << 4);

    for (int s = 0; s < S; s++) {
        asm volatile("cp.async.wait_group 1;" ::: "memory");
        __syncthreads();
        if (s + 2 < S)
            load_stage(sb + ((s + 2) % 3) * STG_BYTES, Ab, Bb, lda, ldb,
                       (s + 2) * 64, tid);
        asm volatile("cp.async.commit_group;" ::: "memory");

        uint32_t sa = sb + (s % 3) * STG_BYTES;
        uint32_t sB = sa + A_BYTES;

        uint32_t afr[2][4][4];
#pragma unroll
        for (int i = 0; i < 4; i++)
            ldsm4(afr[0][i][0], afr[0][i][1], afr[0][i][2], afr[0][i][3],
                  sa + (a_row + i * 16) * ROW_B + a_cs);
#pragma unroll
        for (int kk = 0; kk < 4; kk++) {
            int cur = kk & 1;
            if (kk < 3) {
                int nxt = cur ^ 1;
#pragma unroll
                for (int i = 0; i < 4; i++)
                    ldsm4(afr[nxt][i][0], afr[nxt][i][1], afr[nxt][i][2],
                          afr[nxt][i][3],
                          sa + (a_row + i * 16) * ROW_B + (kk + 1) * 32 + a_cs);
            }
            uint32_t b[4][2];
#pragma unroll
            for (int jt = 0; jt < 2; jt++) {
                uint32_t r0, r1, r2, r3;
                ldsm4(r0, r1, r2, r3,
                      sB + (b_row + jt * 16) * ROW_B + kk * 32 + b_cs);
                b[jt * 2][0] = r0; b[jt * 2][1] = r1;
                b[jt * 2 + 1][0] = r2; b[jt * 2 + 1][1] = r3;
            }
#pragma unroll
            for (int i = 0; i < 4; i++)
#pragma unroll
                for (int j = 0; j < 4; j++) mma_bf16(acc[i][j], afr[cur][i], b[j]);
        }
    }

    // ---------------- epilogue ----------------
    float c0v = (mode == 1) ? c0p[0] : 0.0f;
#pragma unroll
    for (int i = 0; i < 4; i++) {
        int r0 = m0 + wm * 64 + i * 16 + (lane >> 2);
        float bm0 = bias_m ? bias_m[r0] : 0.0f;
        float bm1 = bias_m ? bias_m[r0 + 8] : 0.0f;
        float uu0 = 0.0f, uu1 = 0.0f;
        if (mode == 1) {
            uu0 = ub[z * 4096 + r0] + c0v;
            uu1 = ub[z * 4096 + r0 + 8] + c0v;
        }
        float rs0 = 0.0f, rs1 = 0.0f;
#pragma unroll
        for (int j = 0; j < 4; j++) {
            int cc = n0 + wn * 32 + j * 8 + (lane & 3) * 2;
            float v00, v01, v10, v11;
            if (mode == 1) {
                float vv0 = vbp[z * 4096 + cc], vv1 = vbp[z * 4096 + cc + 1];
                v00 = fexp(acc[i][j][0] * alpha + uu0 + vv0);
                v01 = fexp(acc[i][j][1] * alpha + uu0 + vv1);
                v10 = fexp(acc[i][j][2] * alpha + uu1 + vv0);
                v11 = fexp(acc[i][j][3] * alpha + uu1 + vv1);
            } else if (mode == 3) {
                float li0 = __fdividef(1.0f, lsum[z * 4096 + cc]);
                float li1 = __fdividef(1.0f, lsum[z * 4096 + cc + 1]);
                v00 = acc[i][j][0] * li0 + bm0;
                v01 = acc[i][j][1] * li1 + bm0;
                v10 = acc[i][j][2] * li0 + bm1;
                v11 = acc[i][j][3] * li1 + bm1;
            } else {
                v00 = acc[i][j][0] * alpha + bm0;
                v01 = acc[i][j][1] * alpha + bm0;
                v10 = acc[i][j][2] * alpha + bm1;
                v11 = acc[i][j][3] * alpha + bm1;
            }
            int64_t i0 = (int64_t)z * cstr + (int64_t)r0 * ldc + cc;
            int64_t i1 = i0 + 8 * ldc;
            if (out_f32) {
                float* Cf = (float*)C;
                if (resid) {
                    float2 t0 = *(const float2*)(resid + i0);
                    float2 t1 = *(const float2*)(resid + i1);
                    v00 += t0.x; v01 += t0.y; v10 += t1.x; v11 += t1.y;
                }
                *(float2*)(Cf + i0) = make_float2(v00, v01);
                *(float2*)(Cf + i1) = make_float2(v10, v11);
            } else {
                __nv_bfloat16* Cb = (__nv_bfloat16*)C;
                __nv_bfloat162 h0 = __float22bfloat162_rn(make_float2(v00, v01));
                __nv_bfloat162 h1 = __float22bfloat162_rn(make_float2(v10, v11));
                if (mode == 1) {
                    float2 q0 = __bfloat1622float2(h0);
                    float2 q1 = __bfloat1622float2(h1);
                    rs0 += q0.x + q0.y;
                    rs1 += q1.x + q1.y;
                }
                *(__nv_bfloat162*)(Cb + i0) = h0;
                *(__nv_bfloat162*)(Cb + i1) = h1;
            }
        }
        if (mode == 1) {
            rs0 += __shfl_xor_sync(0xffffffffu, rs0, 1);
            rs0 += __shfl_xor_sync(0xffffffffu, rs0, 2);
            rs1 += __shfl_xor_sync(0xffffffffu, rs1, 1);
            rs1 += __shfl_xor_sync(0xffffffffu, rs1, 2);
            if ((lane & 3) == 0) {
                atomicAdd(lsum + z * 4096 + r0, rs0);
                atomicAdd(lsum + z * 4096 + r0 + 8, rs1);
            }
        }
    }
}

// ---------------- zero l + e12 --------------------------------------------------
__global__ void zero_kernel(float* __restrict__ l, float* __restrict__ e12) {
    if (blockIdx.x < 16) l[blockIdx.x * 1024 + threadIdx.x] = 0.0f;
    else e12[threadIdx.x] = 0.0f;
}

// ---------------- e1/e2 via coalesced e-chunk accumulation ----------------------
// e1[c] = scale * sum_e wq[e][c]*bk[e]; e2[c] = scale * sum_e wk[e][c]*bq[e]
__global__ void __launch_bounds__(256) e12_kernel(
    const float* __restrict__ wq, const float* __restrict__ wk,
    const float* __restrict__ bq, const float* __restrict__ bk,
    float* __restrict__ e12, float scale)
{
    int c = threadIdx.x * 2;
    int e0 = blockIdx.x * 64;
    float a0 = 0.f, a1 = 0.f, b0 = 0.f, b1 = 0.f;
#pragma unroll 4
    for (int e = e0; e < e0 + 64; e++) {
        float bke = bk[e], bqe = bq[e];
        float2 w1 = *(const float2*)(wq + (int64_t)e * 512 + c);
        float2 w2 = *(const float2*)(wk + (int64_t)e * 512 + c);
        a0 += w1.x * bke; a1 += w1.y * bke;
        b0 += w2.x * bqe; b1 += w2.y * bqe;
    }
    atomicAdd(e12 + c, a0 * scale);
    atomicAdd(e12 + c + 1, a1 * scale);
    atomicAdd(e12 + 512 + c, b0 * scale);
    atomicAdd(e12 + 512 + c + 1, b1 * scale);
}

// ---------------- bpp = Wp bv + bp ; c0 = scale*(bq.bk) -------------------------
__global__ void __launch_bounds__(256) bppc0_kernel(
    const float* __restrict__ wp, const float* __restrict__ bq,
    const float* __restrict__ bk, const float* __restrict__ bv,
    const float* __restrict__ bp, float* __restrict__ bpp,
    float* __restrict__ c0, float scale)
{
    int wid = threadIdx.x >> 5, lane = threadIdx.x & 31;
    int c = blockIdx.x * 8 + wid;
    float s3 = 0.f, s4 = 0.f;
    for (int e = lane; e < 512; e += 32) {
        s3 += wp[(int64_t)c * 512 + e] * bv[e];
        if (blockIdx.x == 0 && wid == 0) s4 += bq[e] * bk[e];
    }
#pragma unroll
    for (int o = 16; o; o >>= 1) {
        s3 += __shfl_xor_sync(0xffffffffu, s3, o);
        s4 += __shfl_xor_sync(0xffffffffu, s4, o);
    }
    if (lane == 0) {
        bpp[c] = s3 + bp[c];
        if (blockIdx.x == 0 && wid == 0) c0[0] = s4 * scale;
    }
}

// ---------------- weight prep: transpose+cvt wq,wk,wv; plain cvt wp ------------
__global__ void __launch_bounds__(256) prep_w_kernel(
    const float* __restrict__ wq, const float* __restrict__ wk,
    const float* __restrict__ wv, const float* __restrict__ wp,
    __nv_bfloat16* __restrict__ wqT, __nv_bfloat16* __restrict__ wkT,
    __nv_bfloat16* __restrict__ wvT, __nv_bfloat16* __restrict__ wpB)
{
    __shared__ float t[32][33];
    int zz = blockIdx.z;
    const float* src = zz == 0 ? wq : zz == 1 ? wk : zz == 2 ? wv : wp;
    int x0 = blockIdx.x * 32, y0 = blockIdx.y * 32;
    int tx = threadIdx.x & 31, ty = threadIdx.x >> 5;
    for (int r = ty; r < 32; r += 8)
        t[r][tx] = src[(int64_t)(y0 + r) * 512 + x0 + tx];
    __syncthreads();
    if (zz < 3) {
        __nv_bfloat16* dst = zz == 0 ? wqT : zz == 1 ? wkT : wvT;
        for (int r = ty; r < 32; r += 8)
            dst[(int64_t)(x0 + r) * 512 + y0 + tx] = __float2bfloat16(t[tx][r]);
    } else {
        for (int r = ty; r < 32; r += 8)
            wpB[(int64_t)(y0 + r) * 512 + x0 + tx] = __float2bfloat16(t[r][tx]);
    }
}

// ---------------- GEMV: u[z][i] = ht_i . e1 ; v[z][i] = ht_i . e2 --------------
__global__ void __launch_bounds__(256) gemv_uv_kernel(
    const __nv_bfloat16* __restrict__ ht, const float* __restrict__ e12,
    float* __restrict__ u, float* __restrict__ vb)
{
    int z = blockIdx.y;
    int row = blockIdx.x * 8 + (threadIdx.x >> 5);
    int lane = threadIdx.x & 31;
    const __nv_bfloat16* hr = ht + (int64_t)z * 2097152 + (int64_t)row * 512;
    float s1 = 0.f, s2 = 0.f;
    for (int c = lane * 2; c < 512; c += 64) {
        float2 h = __bfloat1622float2(*(const __nv_bfloat162*)(hr + c));
        s1 += h.x * e12[c] + h.y * e12[c + 1];
        s2 += h.x * e12[512 + c] + h.y * e12[512 + c + 1];
    }
#pragma unroll
    for (int o = 16; o; o >>= 1) {
        s1 += __shfl_xor_sync(0xffffffffu, s1, o);
        s2 += __shfl_xor_sync(0xffffffffu, s2, o);
    }
    if (lane == 0) {
        u[z * 4096 + row] = s1;
        vb[z * 4096 + row] = s2;
    }
}

// ---------------- GroupNorm -> transposed bf16 H^T [b][l][c] -------------------
__global__ void __launch_bounds__(256) groupnorm_t_kernel(
    const float* __restrict__ x, const float* __restrict__ scale,
    const float* __restrict__ bias, __nv_bfloat16* __restrict__ ht)
{
    __shared__ float tile[16 * 257];
    __shared__ float sh_s[8], sh_ss[8], s_stat[2];
    __shared__ float csc[16], cbi[16];

    int bi = blockIdx.x;
    int b = bi >> 5, g = bi & 31;
    const float* xg = x + (size_t)bi * 65536;

    float s = 0.f, ss = 0.f;
    const float4* xp = (const float4*)xg;
    for (int i = threadIdx.x; i < 16384; i += 256) {
        float4 t = xp[i];
        s  += t.x + t.y + t.z + t.w;
        ss += t.x * t.x + t.y * t.y + t.z * t.z + t.w * t.w;
    }
    int lane = threadIdx.x & 31, wrp = threadIdx.x >> 5;
#pragma unroll
    for (int o = 16; o; o >>= 1) {
        s  += __shfl_xor_sync(0xffffffffu, s, o);
        ss += __shfl_xor_sync(0xffffffffu, ss, o);
    }
    if (lane == 0) { sh_s[wrp] = s; sh_ss[wrp] = ss; }
    __syncthreads();
    if (threadIdx.x == 0) {
        float ts = 0.f, tss = 0.f;
        for (int i = 0; i < 8; i++) { ts += sh_s[i]; tss += sh_ss[i]; }
        float mean = ts / 65536.0f;
        float var  = tss / 65536.0f - mean * mean;
        s_stat[0] = mean;
        s_stat[1] = rsqrtf(var + 1e-6f);
    }
    __syncthreads();
    if (threadIdx.x < 16) {
        float sc = scale[g * 16 + threadIdx.x] * s_stat[1];
        csc[threadIdx.x] = sc;
        cbi[threadIdx.x] = bias[g * 16 + threadIdx.x] - s_stat[0] * sc;
    }
    __syncthreads();

    __nv_bfloat16* hb = ht + (size_t)b * 2097152 + g * 16;
    for (int l0 = 0; l0 < 4096; l0 += 256) {
#pragma unroll
        for (int c = 0; c < 16; c++)
            tile[c * 257 + threadIdx.x] =
                xg[c * 4096 + l0 + threadIdx.x] * csc[c] + cbi[c];
        __syncthreads();
#pragma unroll
        for (int rep = 0; rep < 16; rep++) {
            int idx = rep * 256 + threadIdx.x;
            int lp = idx >> 4, cc = idx & 15;
            hb[(size_t)(l0 + lp) * 512 + cc] =
                __float2bfloat16(tile[cc * 257 + lp]);
        }
        __syncthreads();
    }
}

// -----------------------------------------------------------------------------
extern "C" void kernel_launch(void* const* d_in, const int* in_sizes, int n_in,
                              void* d_out, int out_size)
{
    (void)in_sizes; (void)n_in; (void)out_size;
    const float* x  = (const float*)d_in[0];
    const float* gs = (const float*)d_in[1];
    const float* gb = (const float*)d_in[2];
    const float* wq = (const float*)d_in[3];
    const float* bq = (const float*)d_in[4];
    const float* wk = (const float*)d_in[5];
    const float* bk = (const float*)d_in[6];
    const float* wv = (const float*)d_in[7];
    const float* bv = (const float*)d_in[8];
    const float* wp = (const float*)d_in[9];
    const float* bp = (const float*)d_in[10];
    float* out = (float*)d_out;

    __nv_bfloat16 *ht, *nkt, *v2, *s, *wqT, *wkT, *wvT, *wpB, *Mb, *W2;
    float *l, *u, *vb, *e12, *bpp, *c0;
    cudaGetSymbolAddress((void**)&ht, g_ht);
    cudaGetSymbolAddress((void**)&nkt, g_nkt);
    cudaGetSymbolAddress((void**)&v2, g_v2);
    cudaGetSymbolAddress((void**)&s,  g_s);
    cudaGetSymbolAddress((void**)&wqT, g_wqT);
    cudaGetSymbolAddress((void**)&wkT, g_wkT);
    cudaGetSymbolAddress((void**)&wvT, g_wvT);
    cudaGetSymbolAddress((void**)&wpB, g_wpB);
    cudaGetSymbolAddress((void**)&Mb, g_M);
    cudaGetSymbolAddress((void**)&W2, g_W2);
    cudaGetSymbolAddress((void**)&l,  g_l);
    cudaGetSymbolAddress((void**)&u,  g_u);
    cudaGetSymbolAddress((void**)&vb, g_vb);
    cudaGetSymbolAddress((void**)&e12, g_e12);
    cudaGetSymbolAddress((void**)&bpp, g_bpp);
    cudaGetSymbolAddress((void**)&c0, g_c0);

    static cudaStream_t s2 = nullptr;
    static cudaEvent_t evStart = nullptr, evGn = nullptr, evE12 = nullptr,
                       evM = nullptr, evV2 = nullptr;
    if (!s2) {
        cudaStreamCreateWithFlags(&s2, cudaStreamNonBlocking);
        cudaEventCreateWithFlags(&evStart, cudaEventDisableTiming);
        cudaEventCreateWithFlags(&evGn, cudaEventDisableTiming);
        cudaEventCreateWithFlags(&evE12, cudaEventDisableTiming);
        cudaEventCreateWithFlags(&evM, cudaEventDisableTiming);
        cudaEventCreateWithFlags(&evV2, cudaEventDisableTiming);
        cudaFuncSetAttribute(mm_bf16,
                             cudaFuncAttributeMaxDynamicSharedMemorySize,
                             SMEM_TOTAL);
    }

    const float SCALE = 0.044194173824159216f;  // 512^-0.5
    const int64_t LC = 2097152, LS = 16777216;

    // fork
    cudaEventRecord(evStart, 0);
    cudaStreamWaitEvent(s2, evStart, 0);

    // s0: groupnorm
    groupnorm_t_kernel<<<128, 256>>>(x, gs, gb, ht);
    cudaEventRecord(evGn, 0);

    // s2: weight-side chain
    zero_kernel<<<17, 1024, 0, s2>>>(l, e12);
    e12_kernel<<<8, 256, 0, s2>>>(wq, wk, bq, bk, e12, SCALE);
    cudaEventRecord(evE12, s2);
    bppc0_kernel<<<64, 256, 0, s2>>>(wp, bq, bk, bv, bp, bpp, c0, SCALE);
    prep_w_kernel<<<dim3(16, 16, 4), 256, 0, s2>>>(wq, wk, wv, wp,
                                                   wqT, wkT, wvT, wpB);
    // M[c][d] = sum_e wq[e][c] wk[e][d]
    mm_bf16<<<dim3(4, 4, 1), 256, SMEM_TOTAL, s2>>>(wqT, 512, 0, wkT, 512, 0,
        Mb, 512, 0, 512, 1.0f, nullptr, nullptr, nullptr, nullptr, nullptr,
        nullptr, 0, 0);
    cudaEventRecord(evM, s2);
    // W2[c][d] = sum_e wp[c][e] wv[e][d]
    mm_bf16<<<dim3(4, 4, 1), 256, SMEM_TOTAL, s2>>>(wpB, 512, 0, wvT, 512, 0,
        W2, 512, 0, 512, 1.0f, nullptr, nullptr, nullptr, nullptr, nullptr,
        nullptr, 0, 0);
    // V2[c][j] = sum_d W2[c][d] ht[j][d]  (needs gn)
    cudaStreamWaitEvent(s2, evGn, 0);
    mm_bf16<<<dim3(32, 4, 4), 256, SMEM_TOTAL, s2>>>(W2, 512, 0, ht, 512, LC,
        v2, 4096, LC, 512, 1.0f, nullptr, nullptr, nullptr, nullptr, nullptr,
        nullptr, 0, 0);
    cudaEventRecord(evV2, s2);

    // s0: gemv (needs gn + e12; e12 implies zero done)
    cudaStreamWaitEvent(0, evE12, 0);
    gemv_uv_kernel<<<dim3(512, 4), 256>>>(ht, e12, u, vb);
    // N[j][c'] = sum_d M[c'][d] ht[j][d] (needs M)
    cudaStreamWaitEvent(0, evM, 0);
    mm_bf16<<<dim3(4, 32, 4), 256, SMEM_TOTAL>>>(ht, 512, LC, Mb, 512, 0,
        nkt, 512, LC, 512, 1.0f, nullptr, nullptr, nullptr, nullptr, nullptr,
        nullptr, 0, 0);
    // P[i][j] = exp(scale*acc + u_i + v_j + c0) (+ row sums into l)
    mm_bf16<<<dim3(32, 32, 4), 256, SMEM_TOTAL>>>(ht, 512, LC, nkt, 512, LC,
        s, 4096, LS, 512, SCALE, nullptr, u, vb, c0, nullptr, l, 1, 0);
    // out[c][i] = (sum_j V2[c][j] P[i][j]) / l[i] + bpp[c] + x[c][i]
    cudaStreamWaitEvent(0, evV2, 0);
    mm_bf16<<<dim3(32, 4, 4), 256, SMEM_TOTAL>>>(v2, 4096, LC, s, 4096, LS,
        out, 4096, LC, 4096, 1.0f, bpp, nullptr, nullptr, nullptr, x, l, 3, 1);
}